// round 1
// baseline (speedup 1.0000x reference)
#include <cuda_runtime.h>
#include <cstdint>

// Problem dims (fixed)
#define TOK   8192      // B*N
#define DIM   1024      // D
#define NCB   64        // C codebooks
#define KD    16        // K
#define NP    64        // P keys
#define MV    128       // M
#define NR    8         // R
#define NPROJ 2048      // 2 branches * C*K

// 64 MB scratch for projections: proj[t][n], n = branch*1024 + c*16 + k
__device__ float g_proj[(size_t)TOK * NPROJ];

// ---------------------------------------------------------------------------
// Kernel 1: fp32 SGEMM  proj[t, n] = sum_d x[t,d] * W[n,d]
//   W rows 0..1023   -> W_A flattened [C*K, D]
//   W rows 1024..2047 -> W_B flattened
// 128x128 tile, BK=8, 256 threads, 8x8 micro-tile.
// ---------------------------------------------------------------------------
__global__ __launch_bounds__(256) void proj_gemm(
    const float* __restrict__ X,
    const float* __restrict__ WA,
    const float* __restrict__ WB,
    float* __restrict__ out)
{
    const int n0 = blockIdx.x * 128;   // 0..1920
    const int t0 = blockIdx.y * 128;   // 0..8064
    const float* __restrict__ W = (n0 < 1024) ? (WA + (size_t)n0 * DIM)
                                              : (WB + (size_t)(n0 - 1024) * DIM);

    __shared__ float As[8][128];
    __shared__ float Bs[8][128];

    const int tid = threadIdx.x;
    const int tx = tid & 15;       // 0..15 -> n
    const int ty = tid >> 4;       // 0..15 -> t
    const int lr = tid >> 1;       // 0..127 load row
    const int lc = (tid & 1) * 4;  // 0 or 4 load col

    float acc[8][8];
    #pragma unroll
    for (int i = 0; i < 8; i++)
        #pragma unroll
        for (int j = 0; j < 8; j++) acc[i][j] = 0.f;

    const float* aptr = X + (size_t)(t0 + lr) * DIM + lc;
    const float* bptr = W + (size_t)lr * DIM + lc;

    for (int k0 = 0; k0 < DIM; k0 += 8) {
        float4 av = *(const float4*)(aptr + k0);
        float4 bv = *(const float4*)(bptr + k0);
        __syncthreads();
        As[lc + 0][lr] = av.x; As[lc + 1][lr] = av.y;
        As[lc + 2][lr] = av.z; As[lc + 3][lr] = av.w;
        Bs[lc + 0][lr] = bv.x; Bs[lc + 1][lr] = bv.y;
        Bs[lc + 2][lr] = bv.z; Bs[lc + 3][lr] = bv.w;
        __syncthreads();
        #pragma unroll
        for (int kk = 0; kk < 8; kk++) {
            float ra[8], rb[8];
            #pragma unroll
            for (int i = 0; i < 8; i++) ra[i] = As[kk][ty * 8 + i];
            #pragma unroll
            for (int j = 0; j < 8; j++) rb[j] = Bs[kk][tx * 8 + j];
            #pragma unroll
            for (int i = 0; i < 8; i++)
                #pragma unroll
                for (int j = 0; j < 8; j++)
                    acc[i][j] = fmaf(ra[i], rb[j], acc[i][j]);
        }
    }

    #pragma unroll
    for (int i = 0; i < 8; i++) {
        float* orow = out + (size_t)(t0 + ty * 8 + i) * NPROJ + n0 + tx * 8;
        float4 v0 = make_float4(acc[i][0], acc[i][1], acc[i][2], acc[i][3]);
        float4 v1 = make_float4(acc[i][4], acc[i][5], acc[i][6], acc[i][7]);
        *(float4*)(orow + 0) = v0;
        *(float4*)(orow + 4) = v1;
    }
}

// ---------------------------------------------------------------------------
// Kernel 2: fused argmin + gather-dot + output.  8 tokens per block.
// smem: proj (8*2048 f), x (8*1024 f), sA (8*64 f), t (8*8 f), idxA/idxB ints
// ---------------------------------------------------------------------------
#define GTOK 8
#define FUSE_SMEM ((GTOK*NPROJ + GTOK*DIM + GTOK*NCB + GTOK*NR) * 4 + 2*GTOK*NCB * 4)

__global__ __launch_bounds__(256) void fuse_kernel(
    const float* __restrict__ x,
    const float* __restrict__ emb_A, const float* __restrict__ vals_A,
    const float* __restrict__ emb_B, const float* __restrict__ vals_B,
    float* __restrict__ out)
{
    extern __shared__ float sm[];
    float* proj_s = sm;                         // GTOK*2048
    float* x_s    = proj_s + GTOK * NPROJ;      // GTOK*1024
    float* sA     = x_s + GTOK * DIM;           // GTOK*64
    float* tb     = sA + GTOK * NCB;            // GTOK*8
    int*   idxA   = (int*)(tb + GTOK * NR);     // GTOK*64
    int*   idxB   = idxA + GTOK * NCB;          // GTOK*64

    const int tid  = threadIdx.x;
    const int warp = tid >> 5;
    const int lane = tid & 31;
    const int tok0 = blockIdx.x * GTOK;

    // stage x and proj
    {
        const float4* src = (const float4*)(x + (size_t)tok0 * DIM);
        float4* dst = (float4*)x_s;
        #pragma unroll
        for (int i = tid; i < GTOK * DIM / 4; i += 256) dst[i] = src[i];
        const float4* psrc = (const float4*)(g_proj + (size_t)tok0 * NPROJ);
        float4* pdst = (float4*)proj_s;
        #pragma unroll
        for (int i = tid; i < GTOK * NPROJ / 4; i += 256) pdst[i] = psrc[i];
    }
    __syncthreads();

    // ---- distance + argmin: 128 (branch, codebook) pairs over 8 warps ----
    for (int pair = warp; pair < 2 * NCB; pair += 8) {
        const int br = pair >> 6;
        const int c  = pair & 63;
        const float* emb = br ? emb_B : emb_A;
        // two key rows per lane: p0 = lane, p1 = lane+32 (held in regs, reused for 8 tokens)
        float e0[KD], e1[KD];
        {
            const float4* r0 = (const float4*)(emb + ((size_t)c * NP + lane) * KD);
            const float4* r1 = r0 + 32 * KD / 4;
            #pragma unroll
            for (int q = 0; q < 4; q++) {
                float4 v0 = r0[q], v1 = r1[q];
                e0[q*4+0]=v0.x; e0[q*4+1]=v0.y; e0[q*4+2]=v0.z; e0[q*4+3]=v0.w;
                e1[q*4+0]=v1.x; e1[q*4+1]=v1.y; e1[q*4+2]=v1.z; e1[q*4+3]=v1.w;
            }
        }
        float ee0 = 0.f, ee1 = 0.f;
        #pragma unroll
        for (int k = 0; k < KD; k++) { ee0 = fmaf(e0[k], e0[k], ee0); ee1 = fmaf(e1[k], e1[k], ee1); }

        for (int g = 0; g < GTOK; g++) {
            const float* pr = proj_s + g * NPROJ + br * 1024 + c * KD;
            float pp = 0.f, d0 = 0.f, d1 = 0.f;
            #pragma unroll
            for (int k = 0; k < KD; k++) {
                float p = pr[k];
                pp = fmaf(p, p, pp);
                d0 = fmaf(p, e0[k], d0);
                d1 = fmaf(p, e1[k], d1);
            }
            // mimic reference expression: (pp - 2*dot) + ee
            float s0 = (pp - 2.0f * d0) + ee0;
            float s1 = (pp - 2.0f * d1) + ee1;
            float best = s0; int bi = lane;
            if (s1 < best) { best = s1; bi = lane + 32; }
            #pragma unroll
            for (int off = 16; off > 0; off >>= 1) {
                float os = __shfl_xor_sync(0xffffffffu, best, off);
                int   oi = __shfl_xor_sync(0xffffffffu, bi, off);
                if (os < best || (os == best && oi < bi)) { best = os; bi = oi; }
            }
            if (lane == 0) (br ? idxB : idxA)[g * NCB + c] = bi;
        }
    }
    __syncthreads();

    // ---- s_A[c] = dot(x_chunk[c%8], vals_A[c, idxA[c]]) ----
    for (int c = warp; c < NCB; c += 8) {
        const int chunk = c & 7;
        for (int g = 0; g < GTOK; g++) {
            const int id = idxA[g * NCB + c];
            const float* vr = vals_A + ((size_t)c * NP + id) * MV;
            const float* xr = x_s + g * DIM + chunk * MV;
            float acc = 0.f;
            #pragma unroll
            for (int j = 0; j < 4; j++) {
                int m = lane + 32 * j;
                acc = fmaf(xr[m], __ldg(vr + m), acc);
            }
            #pragma unroll
            for (int off = 16; off > 0; off >>= 1)
                acc += __shfl_xor_sync(0xffffffffu, acc, off);
            if (lane == 0) sA[g * NCB + c] = acc;
        }
    }
    __syncthreads();

    // ---- t[g][r] = sum of 8 consecutive s ----
    if (tid < GTOK * NR) {
        const int g = tid >> 3, r = tid & 7;
        float acc = 0.f;
        #pragma unroll
        for (int i = 0; i < 8; i++) acc += sA[g * NCB + r * 8 + i];
        tb[g * NR + r] = acc;
    }
    __syncthreads();

    // ---- out[token][h*128+m] = sum_r t[r] * vals_B[8r+h, idxB[8r+h], m] ----
    for (int g = 0; g < GTOK; g++) {
        float tr[NR];
        #pragma unroll
        for (int r = 0; r < NR; r++) tr[r] = tb[g * NR + r];
        float* orow = out + (size_t)(tok0 + g) * DIM;
        #pragma unroll
        for (int j = 0; j < 4; j++) {
            const int d = tid + 256 * j;
            const int h = d >> 7, m = d & 127;
            float acc = 0.f;
            #pragma unroll
            for (int r = 0; r < NR; r++) {
                const int c = 8 * r + h;
                acc = fmaf(tr[r],
                           __ldg(vals_B + ((size_t)c * NP + idxB[g * NCB + c]) * MV + m),
                           acc);
            }
            orow[d] = acc;
        }
    }
}

// ---------------------------------------------------------------------------
extern "C" void kernel_launch(void* const* d_in, const int* in_sizes, int n_in,
                              void* d_out, int out_size)
{
    (void)in_sizes; (void)n_in; (void)out_size;
    const float* x      = (const float*)d_in[0];
    const float* W_A    = (const float*)d_in[1];
    const float* emb_A  = (const float*)d_in[2];
    const float* vals_A = (const float*)d_in[3];
    const float* W_B    = (const float*)d_in[4];
    const float* emb_B  = (const float*)d_in[5];
    const float* vals_B = (const float*)d_in[6];
    float* out = (float*)d_out;

    float* proj;
    cudaGetSymbolAddress((void**)&proj, g_proj);

    static bool attr_set = false;
    if (!attr_set) {
        cudaFuncSetAttribute(fuse_kernel,
                             cudaFuncAttributeMaxDynamicSharedMemorySize, FUSE_SMEM);
        attr_set = true;
    }

    dim3 gg(NPROJ / 128, TOK / 128);
    proj_gemm<<<gg, 256>>>(x, W_A, W_B, proj);
    fuse_kernel<<<TOK / GTOK, 256, FUSE_SMEM>>>(x, emb_A, vals_A, emb_B, vals_B, out);
}